// round 1
// baseline (speedup 1.0000x reference)
#include <cuda_runtime.h>
#include <math.h>

// Problem constants (fixed shapes)
constexpr int Bsz  = 2;
constexpr int Sseq = 2048;
constexpr int Fdim = 1024;
constexpr int Hh   = 16;
constexpr int Dh   = 64;
constexpr int Mrows = Bsz * Sseq;   // 4096

// Scratch (allocation-free: device globals). 4 x 16MB.
__device__ float g_Q[(size_t)Mrows * Fdim];
__device__ float g_K[(size_t)Mrows * Fdim];
__device__ float g_V[(size_t)Mrows * Fdim];
__device__ float g_O[(size_t)Mrows * Fdim];

// ---------------------------------------------------------------------------
// SGEMM: C[M,N] = A[M,K] @ W[K,N] + bias[N]
// 128x128 tile, BK=8, 256 threads, 8x8 register micro-tile.
// MODE 0: write C0[m*N+n].
// MODE 1: (KV split, N=2048) n<1024 -> C0[m*1024+n]; else C1[m*1024+n-1024].
// ---------------------------------------------------------------------------
template <int MODE>
__global__ __launch_bounds__(256) void sgemm_kernel(
    const float* __restrict__ A, const float* __restrict__ W,
    const float* __restrict__ bias, float* __restrict__ C0,
    float* __restrict__ C1, int Mm, int Nn, int Kk)
{
    __shared__ float As[8][128];
    __shared__ float Bs[8][128];

    const int tid = threadIdx.x;
    const int m0 = blockIdx.y * 128;
    const int n0 = blockIdx.x * 128;
    const int ty = tid >> 4;        // 0..15
    const int tx = tid & 15;        // 0..15

    const int arow = tid >> 1;      // 0..127
    const int acol = (tid & 1) * 4; // 0 or 4
    const int brow = tid >> 5;      // 0..7
    const int bcol = (tid & 31) * 4;

    float acc[8][8];
    #pragma unroll
    for (int i = 0; i < 8; i++)
        #pragma unroll
        for (int j = 0; j < 8; j++) acc[i][j] = 0.f;

    for (int k0 = 0; k0 < Kk; k0 += 8) {
        float4 av = *(const float4*)&A[(size_t)(m0 + arow) * Kk + k0 + acol];
        As[acol + 0][arow] = av.x;
        As[acol + 1][arow] = av.y;
        As[acol + 2][arow] = av.z;
        As[acol + 3][arow] = av.w;
        *(float4*)&Bs[brow][bcol] =
            *(const float4*)&W[(size_t)(k0 + brow) * Nn + n0 + bcol];
        __syncthreads();

        #pragma unroll
        for (int kk = 0; kk < 8; kk++) {
            float a[8], b[8];
            *(float4*)&a[0] = *(float4*)&As[kk][ty * 8];
            *(float4*)&a[4] = *(float4*)&As[kk][ty * 8 + 4];
            *(float4*)&b[0] = *(float4*)&Bs[kk][tx * 8];
            *(float4*)&b[4] = *(float4*)&Bs[kk][tx * 8 + 4];
            #pragma unroll
            for (int i = 0; i < 8; i++)
                #pragma unroll
                for (int j = 0; j < 8; j++)
                    acc[i][j] += a[i] * b[j];
        }
        __syncthreads();
    }

    #pragma unroll
    for (int i = 0; i < 8; i++) {
        const int m = m0 + ty * 8 + i;
        #pragma unroll
        for (int j = 0; j < 8; j++) {
            const int n = n0 + tx * 8 + j;
            const float v = acc[i][j] + bias[n];
            if (MODE == 0) {
                C0[(size_t)m * Nn + n] = v;
            } else {
                if (n < 1024) C0[(size_t)m * 1024 + n] = v;
                else          C1[(size_t)m * 1024 + (n - 1024)] = v;
            }
        }
    }
}

// ---------------------------------------------------------------------------
// Flash attention, fp32, Br=Bc=64, d=64. Mask: z >= s -> logit = -1e12f
// (constant; matches reference fp32 rounding of logit - 1e12, making the
// fully-masked row s=0 a uniform softmax over all Z keys).
// Grid: (S/64, H, B). 256 threads; 16x16 thread layout, 4x4 micro-tiles.
// Dynamic smem: Qs[64][64] + Ks[64][65] (aliased as Ps) + Vs[64][64].
// ---------------------------------------------------------------------------
__global__ __launch_bounds__(256) void flash_kernel(
    const float* __restrict__ Q, const float* __restrict__ K,
    const float* __restrict__ V, float* __restrict__ O)
{
    extern __shared__ float sm[];
    float* Qs = sm;                 // [64][64]
    float* Ks = sm + 64 * 64;       // [64][65] (reused as Ps)
    float* Vs = Ks + 64 * 65;       // [64][64]

    const int t = blockIdx.x;
    const int h = blockIdx.y;
    const int b = blockIdx.z;
    const int tid = threadIdx.x;
    const int tx = tid & 15;
    const int ty = tid >> 4;
    const int i0 = ty * 4;          // query rows within tile
    const int j0 = tx * 4;          // key cols (S-gemm) / head-dim cols (O-gemm)

    const float* Qg = Q + ((size_t)b * Sseq + (size_t)t * 64) * Fdim + h * Dh;
    const float* Kg = K + ((size_t)b * Sseq) * Fdim + h * Dh;
    const float* Vg = V + ((size_t)b * Sseq) * Fdim + h * Dh;

    // Load Q tile (natural [row][d] layout, float4)
    #pragma unroll
    for (int r = 0; r < 4; r++) {
        const int idx = tid + r * 256;
        const int row = idx >> 4;
        const int c = (idx & 15) * 4;
        *(float4*)&Qs[row * 64 + c] = *(const float4*)&Qg[(size_t)row * Fdim + c];
    }

    float m[4], l[4], o_acc[4][4];
    #pragma unroll
    for (int i = 0; i < 4; i++) {
        m[i] = -3.0e38f;
        l[i] = 0.f;
        #pragma unroll
        for (int j = 0; j < 4; j++) o_acc[i][j] = 0.f;
    }

    // tile 0 must cover all Z (row s=0 is fully masked -> uniform softmax);
    // tile t>0 needs key tiles 0..t only.
    const int nkc = (t == 0) ? (Sseq / 64) : (t + 1);

    for (int kc = 0; kc < nkc; kc++) {
        __syncthreads();   // prior iter's Ps/Vs reads complete before overwrite
        #pragma unroll
        for (int r = 0; r < 4; r++) {
            const int idx = tid + r * 256;
            const int row = idx >> 4;
            const int c = (idx & 15) * 4;
            const size_t grow = (size_t)(kc * 64 + row) * Fdim + c;
            float4 k4 = *(const float4*)&Kg[grow];
            Ks[row * 65 + c + 0] = k4.x;
            Ks[row * 65 + c + 1] = k4.y;
            Ks[row * 65 + c + 2] = k4.z;
            Ks[row * 65 + c + 3] = k4.w;
            *(float4*)&Vs[row * 64 + c] = *(const float4*)&Vg[grow];
        }
        __syncthreads();

        // S = Q @ K^T  (64x64 tile, 4x4 per thread)
        float s_acc[4][4];
        #pragma unroll
        for (int i = 0; i < 4; i++)
            #pragma unroll
            for (int j = 0; j < 4; j++) s_acc[i][j] = 0.f;

        #pragma unroll 8
        for (int d = 0; d < 64; d++) {
            float a[4], kk[4];
            #pragma unroll
            for (int i = 0; i < 4; i++) a[i] = Qs[(i0 + i) * 64 + d];
            #pragma unroll
            for (int j = 0; j < 4; j++) kk[j] = Ks[(j0 + j) * 65 + d];
            #pragma unroll
            for (int i = 0; i < 4; i++)
                #pragma unroll
                for (int j = 0; j < 4; j++)
                    s_acc[i][j] += a[i] * kk[j];
        }

        // Mask: z >= s  ->  -1e12 (constant)
        const int sbase = t * 64 + i0;
        const int zbase = kc * 64 + j0;
        #pragma unroll
        for (int i = 0; i < 4; i++)
            #pragma unroll
            for (int j = 0; j < 4; j++)
                if (zbase + j >= sbase + i) s_acc[i][j] = -1.0e12f;

        // Online softmax (row stats reduced across the 16 tx lanes; the 16
        // threads sharing a ty live in one half-warp -> shfl width 16)
        #pragma unroll
        for (int i = 0; i < 4; i++) {
            float mt = fmaxf(fmaxf(s_acc[i][0], s_acc[i][1]),
                             fmaxf(s_acc[i][2], s_acc[i][3]));
            #pragma unroll
            for (int o = 8; o > 0; o >>= 1)
                mt = fmaxf(mt, __shfl_xor_sync(0xffffffffu, mt, o, 16));
            const float mn = fmaxf(m[i], mt);
            const float sc = __expf(m[i] - mn);
            float ls = 0.f;
            #pragma unroll
            for (int j = 0; j < 4; j++) {
                s_acc[i][j] = __expf(s_acc[i][j] - mn);
                ls += s_acc[i][j];
            }
            #pragma unroll
            for (int o = 8; o > 0; o >>= 1)
                ls += __shfl_xor_sync(0xffffffffu, ls, o, 16);
            l[i] = l[i] * sc + ls;
            m[i] = mn;
            #pragma unroll
            for (int j = 0; j < 4; j++) o_acc[i][j] *= sc;
        }

        __syncthreads();   // everyone done reading Ks before Ps overwrite
        float* Ps = Ks;    // alias, [j][i] with pad 65
        #pragma unroll
        for (int i = 0; i < 4; i++)
            #pragma unroll
            for (int j = 0; j < 4; j++)
                Ps[(j0 + j) * 65 + (i0 + i)] = s_acc[i][j];
        __syncthreads();

        // O += P @ V   (cols of o_acc are head-dims j0..j0+3)
        #pragma unroll 8
        for (int j = 0; j < 64; j++) {
            float p[4], v[4];
            #pragma unroll
            for (int i = 0; i < 4; i++) p[i] = Ps[j * 65 + i0 + i];
            *(float4*)&v[0] = *(float4*)&Vs[j * 64 + j0];
            #pragma unroll
            for (int i = 0; i < 4; i++)
                #pragma unroll
                for (int jj = 0; jj < 4; jj++)
                    o_acc[i][jj] += p[i] * v[jj];
        }
    }

    float* Og = O + ((size_t)b * Sseq + (size_t)t * 64) * Fdim + h * Dh;
    #pragma unroll
    for (int i = 0; i < 4; i++) {
        const float inv = 1.f / l[i];
        #pragma unroll
        for (int j = 0; j < 4; j++)
            Og[(size_t)(i0 + i) * Fdim + j0 + j] = o_acc[i][j] * inv;
    }
}

// ---------------------------------------------------------------------------
extern "C" void kernel_launch(void* const* d_in, const int* in_sizes, int n_in,
                              void* d_out, int out_size)
{
    (void)in_sizes; (void)n_in; (void)out_size;
    const float* attend_from = (const float*)d_in[0];
    const float* attend_to   = (const float*)d_in[1];
    const float* w_q   = (const float*)d_in[2];
    const float* b_q   = (const float*)d_in[3];
    const float* w_kv  = (const float*)d_in[4];
    const float* b_kv  = (const float*)d_in[5];
    const float* w_out = (const float*)d_in[6];
    const float* b_out = (const float*)d_in[7];
    float* out = (float*)d_out;

    float *Qp, *Kp, *Vp, *Op;
    cudaGetSymbolAddress((void**)&Qp, g_Q);
    cudaGetSymbolAddress((void**)&Kp, g_K);
    cudaGetSymbolAddress((void**)&Vp, g_V);
    cudaGetSymbolAddress((void**)&Op, g_O);

    const int flash_smem = (64 * 64 + 64 * 65 + 64 * 64) * (int)sizeof(float); // 49408
    cudaFuncSetAttribute(flash_kernel,
                         cudaFuncAttributeMaxDynamicSharedMemorySize, flash_smem);

    // 1) Q projection: [4096,1024] = X @ w_q + b_q
    {
        dim3 grid(Fdim / 128, Mrows / 128);
        sgemm_kernel<0><<<grid, 256>>>(attend_from, w_q, b_q, Qp, nullptr,
                                       Mrows, Fdim, Fdim);
    }
    // 2) KV projection with split epilogue: [4096,2048] = Y @ w_kv + b_kv
    {
        dim3 grid((2 * Fdim) / 128, Mrows / 128);
        sgemm_kernel<1><<<grid, 256>>>(attend_to, w_kv, b_kv, Kp, Vp,
                                       Mrows, 2 * Fdim, Fdim);
    }
    // 3) Fused masked attention
    {
        dim3 grid(Sseq / 64, Hh, Bsz);
        flash_kernel<<<grid, 256, flash_smem>>>(Qp, Kp, Vp, Op);
    }
    // 4) Output projection: out = O @ w_out + b_out
    {
        dim3 grid(Fdim / 128, Mrows / 128);
        sgemm_kernel<0><<<grid, 256>>>(Op, w_out, b_out, out, nullptr,
                                       Mrows, Fdim, Fdim);
    }
}

// round 3
// speedup vs baseline: 1.2130x; 1.2130x over previous
#include <cuda_runtime.h>
#include <math.h>
#include <stdint.h>

// Problem constants (fixed shapes)
constexpr int Bsz  = 2;
constexpr int Sseq = 2048;
constexpr int Fdim = 1024;
constexpr int Hh   = 16;
constexpr int Dh   = 64;
constexpr int Mrows = Bsz * Sseq;   // 4096

// Scratch (allocation-free: device globals). 4 x 16MB.
__device__ float g_Q[(size_t)Mrows * Fdim];
__device__ float g_K[(size_t)Mrows * Fdim];
__device__ float g_V[(size_t)Mrows * Fdim];
__device__ float g_O[(size_t)Mrows * Fdim];

// ---------------------------------------------------------------------------
// 3xTF32 tensor-core GEMM: C[M,N] = A[M,K] @ W[K,N] + bias[N]
// Block tile 128x128, BK=32, 256 threads (8 warps, 64x32 warp tiles),
// cp.async double-buffered smem. Each fp32 operand is split x = hi + lo
// (hi = cvt.rna.tf32), and D accumulates A_lo*B_hi + A_hi*B_lo + A_hi*B_hi
// -> near-fp32 precision (~2^-22/elt) at 3x MMA cost.
// MODE 0: C0[m*Nn+n].  MODE 1 (KV split, Nn=2048): n<1024 -> C0, else C1.
// ---------------------------------------------------------------------------
constexpr int SA = 36;   // As row stride (floats): conflict-free frag loads
constexpr int SB = 132;  // Bs row stride (floats)
constexpr int AS_FLOATS = 128 * SA;          // 4608
constexpr int BS_FLOATS = 32 * SB;           // 4224
constexpr int STAGE_FLOATS = AS_FLOATS + BS_FLOATS;  // 8832
constexpr int GEMM_SMEM = 2 * STAGE_FLOATS * 4;      // 70656 B

__device__ __forceinline__ void cp_async16(uint32_t saddr, const void* gptr) {
    asm volatile("cp.async.cg.shared.global [%0], [%1], 16;"
                 :: "r"(saddr), "l"(gptr));
}
__device__ __forceinline__ void cp_commit() {
    asm volatile("cp.async.commit_group;");
}
__device__ __forceinline__ void cp_wait_all() {
    asm volatile("cp.async.wait_group 0;");
}

__device__ __forceinline__ uint32_t f2tf32(float x) {
    uint32_t r;
    asm("cvt.rna.tf32.f32 %0, %1;" : "=r"(r) : "f"(x));
    return r;
}

__device__ __forceinline__ void mma_tf32(
    float& d0, float& d1, float& d2, float& d3,
    uint32_t a0, uint32_t a1, uint32_t a2, uint32_t a3,
    uint32_t b0, uint32_t b1)
{
    asm volatile(
        "mma.sync.aligned.m16n8k8.row.col.f32.tf32.tf32.f32 "
        "{%0,%1,%2,%3},{%4,%5,%6,%7},{%8,%9},{%0,%1,%2,%3};"
        : "+f"(d0), "+f"(d1), "+f"(d2), "+f"(d3)
        : "r"(a0), "r"(a1), "r"(a2), "r"(a3), "r"(b0), "r"(b1));
}

template <int MODE>
__global__ __launch_bounds__(256) void tf32_gemm_kernel(
    const float* __restrict__ A, const float* __restrict__ W,
    const float* __restrict__ bias, float* __restrict__ C0,
    float* __restrict__ C1, int Kk, int Nn)
{
    extern __shared__ float sm[];
    const uint32_t sbase = (uint32_t)__cvta_generic_to_shared(sm);

    const int tid  = threadIdx.x;
    const int m0   = blockIdx.y * 128;
    const int n0   = blockIdx.x * 128;
    const int warp = tid >> 5;
    const int lane = tid & 31;
    const int wm   = warp & 1;          // 0..1 : 64-row slab
    const int wn   = warp >> 1;         // 0..3 : 32-col slab
    const int rbase = wm * 64;
    const int cbase = wn * 32;
    const int lr = lane >> 2;           // 0..7
    const int lc = lane & 3;            // 0..3

    float acc[4][4][4];
    #pragma unroll
    for (int i = 0; i < 4; i++)
        #pragma unroll
        for (int j = 0; j < 4; j++)
            #pragma unroll
            for (int r = 0; r < 4; r++) acc[i][j][r] = 0.f;

    auto load_tile = [&](int kt, int st) {
        const int k0 = kt * 32;
        const uint32_t sAa = sbase + (uint32_t)(st * STAGE_FLOATS) * 4u;
        const uint32_t sBb = sAa + (uint32_t)AS_FLOATS * 4u;
        #pragma unroll
        for (int r = 0; r < 4; r++) {
            const int slot = r * 256 + tid;
            const int row = slot >> 3, k4 = slot & 7;
            cp_async16(sAa + (uint32_t)(row * SA + k4 * 4) * 4u,
                       &A[(size_t)(m0 + row) * Kk + k0 + k4 * 4]);
        }
        #pragma unroll
        for (int r = 0; r < 4; r++) {
            const int slot = r * 256 + tid;
            const int k = slot >> 5, n4 = slot & 31;
            cp_async16(sBb + (uint32_t)(k * SB + n4 * 4) * 4u,
                       &W[(size_t)(k0 + k) * Nn + n0 + n4 * 4]);
        }
    };

    const int NT = Kk / 32;
    load_tile(0, 0);
    cp_commit();

    for (int kt = 0; kt < NT; kt++) {
        cp_wait_all();
        __syncthreads();
        if (kt + 1 < NT) { load_tile(kt + 1, (kt + 1) & 1); cp_commit(); }

        const float* As = sm + (kt & 1) * STAGE_FLOATS;
        const float* Bs = As + AS_FLOATS;

        #pragma unroll
        for (int ks = 0; ks < 4; ks++) {
            const int kk = ks * 8;
            uint32_t ah[4][4], al[4][4], bh[4][2], bl[4][2];
            #pragma unroll
            for (int mi = 0; mi < 4; mi++) {
                const int rr = rbase + mi * 16 + lr;
                float v0 = As[rr * SA + kk + lc];
                float v1 = As[(rr + 8) * SA + kk + lc];
                float v2 = As[rr * SA + kk + lc + 4];
                float v3 = As[(rr + 8) * SA + kk + lc + 4];
                ah[mi][0] = f2tf32(v0); al[mi][0] = __float_as_uint(v0 - __uint_as_float(ah[mi][0]));
                ah[mi][1] = f2tf32(v1); al[mi][1] = __float_as_uint(v1 - __uint_as_float(ah[mi][1]));
                ah[mi][2] = f2tf32(v2); al[mi][2] = __float_as_uint(v2 - __uint_as_float(ah[mi][2]));
                ah[mi][3] = f2tf32(v3); al[mi][3] = __float_as_uint(v3 - __uint_as_float(ah[mi][3]));
            }
            #pragma unroll
            for (int nj = 0; nj < 4; nj++) {
                const int cc = cbase + nj * 8 + lr;
                float w0 = Bs[(kk + lc) * SB + cc];
                float w1 = Bs[(kk + lc + 4) * SB + cc];
                bh[nj][0] = f2tf32(w0); bl[nj][0] = __float_as_uint(w0 - __uint_as_float(bh[nj][0]));
                bh[nj][1] = f2tf32(w1); bl[nj][1] = __float_as_uint(w1 - __uint_as_float(bh[nj][1]));
            }
            #pragma unroll
            for (int mi = 0; mi < 4; mi++)
                #pragma unroll
                for (int nj = 0; nj < 4; nj++) {
                    // small terms first, then the dominant hi*hi
                    mma_tf32(acc[mi][nj][0], acc[mi][nj][1],
                             acc[mi][nj][2], acc[mi][nj][3],
                             al[mi][0], al[mi][1], al[mi][2], al[mi][3],
                             bh[nj][0], bh[nj][1]);
                    mma_tf32(acc[mi][nj][0], acc[mi][nj][1],
                             acc[mi][nj][2], acc[mi][nj][3],
                             ah[mi][0], ah[mi][1], ah[mi][2], ah[mi][3],
                             bl[nj][0], bl[nj][1]);
                    mma_tf32(acc[mi][nj][0], acc[mi][nj][1],
                             acc[mi][nj][2], acc[mi][nj][3],
                             ah[mi][0], ah[mi][1], ah[mi][2], ah[mi][3],
                             bh[nj][0], bh[nj][1]);
                }
        }
        __syncthreads();
    }

    // Epilogue. For MODE 1 the 128-wide n-block is entirely on one side of
    // the 1024 boundary.
    float* Cb;
    int nshift;
    if (MODE == 0) { Cb = C0; nshift = 0; }
    else if (n0 < 1024) { Cb = C0; nshift = 0; }
    else { Cb = C1; nshift = 1024; }
    const int ldc = (MODE == 0) ? Nn : 1024;

    #pragma unroll
    for (int mi = 0; mi < 4; mi++) {
        const int row = m0 + rbase + mi * 16 + lr;
        #pragma unroll
        for (int nj = 0; nj < 4; nj++) {
            const int col = n0 + cbase + nj * 8 + lc * 2;
            const float bx = bias[col], by = bias[col + 1];
            float2 v0 = make_float2(acc[mi][nj][0] + bx, acc[mi][nj][1] + by);
            float2 v1 = make_float2(acc[mi][nj][2] + bx, acc[mi][nj][3] + by);
            *(float2*)&Cb[(size_t)row * ldc + col - nshift] = v0;
            *(float2*)&Cb[(size_t)(row + 8) * ldc + col - nshift] = v1;
        }
    }
}

// ---------------------------------------------------------------------------
// Flash attention, fp32, Br=Bc=64, d=64. Mask: z >= s -> logit = -1e12f
// (constant; matches reference fp32 rounding of logit - 1e12, making the
// fully-masked row s=0 a uniform softmax over all Z keys).
// Grid: (S/64, H, B). 256 threads; 16x16 thread layout, 4x4 micro-tiles.
// ---------------------------------------------------------------------------
__global__ __launch_bounds__(256) void flash_kernel(
    const float* __restrict__ Q, const float* __restrict__ K,
    const float* __restrict__ V, float* __restrict__ O)
{
    extern __shared__ float smf[];
    float* Qs = smf;                // [64][64]
    float* Ks = smf + 64 * 64;      // [64][65] (reused as Ps)
    float* Vs = Ks + 64 * 65;       // [64][64]

    const int t = blockIdx.x;
    const int h = blockIdx.y;
    const int b = blockIdx.z;
    const int tid = threadIdx.x;
    const int tx = tid & 15;
    const int ty = tid >> 4;
    const int i0 = ty * 4;
    const int j0 = tx * 4;

    const float* Qg = Q + ((size_t)b * Sseq + (size_t)t * 64) * Fdim + h * Dh;
    const float* Kg = K + ((size_t)b * Sseq) * Fdim + h * Dh;
    const float* Vg = V + ((size_t)b * Sseq) * Fdim + h * Dh;

    #pragma unroll
    for (int r = 0; r < 4; r++) {
        const int idx = tid + r * 256;
        const int row = idx >> 4;
        const int c = (idx & 15) * 4;
        *(float4*)&Qs[row * 64 + c] = *(const float4*)&Qg[(size_t)row * Fdim + c];
    }

    float m[4], l[4], o_acc[4][4];
    #pragma unroll
    for (int i = 0; i < 4; i++) {
        m[i] = -3.0e38f;
        l[i] = 0.f;
        #pragma unroll
        for (int j = 0; j < 4; j++) o_acc[i][j] = 0.f;
    }

    const int nkc = (t == 0) ? (Sseq / 64) : (t + 1);

    for (int kc = 0; kc < nkc; kc++) {
        __syncthreads();
        #pragma unroll
        for (int r = 0; r < 4; r++) {
            const int idx = tid + r * 256;
            const int row = idx >> 4;
            const int c = (idx & 15) * 4;
            const size_t grow = (size_t)(kc * 64 + row) * Fdim + c;
            float4 k4 = *(const float4*)&Kg[grow];
            Ks[row * 65 + c + 0] = k4.x;
            Ks[row * 65 + c + 1] = k4.y;
            Ks[row * 65 + c + 2] = k4.z;
            Ks[row * 65 + c + 3] = k4.w;
            *(float4*)&Vs[row * 64 + c] = *(const float4*)&Vg[grow];
        }
        __syncthreads();

        float s_acc[4][4];
        #pragma unroll
        for (int i = 0; i < 4; i++)
            #pragma unroll
            for (int j = 0; j < 4; j++) s_acc[i][j] = 0.f;

        #pragma unroll 8
        for (int d = 0; d < 64; d++) {
            float a[4], kk[4];
            #pragma unroll
            for (int i = 0; i < 4; i++) a[i] = Qs[(i0 + i) * 64 + d];
            #pragma unroll
            for (int j = 0; j < 4; j++) kk[j] = Ks[(j0 + j) * 65 + d];
            #pragma unroll
            for (int i = 0; i < 4; i++)
                #pragma unroll
                for (int j = 0; j < 4; j++)
                    s_acc[i][j] += a[i] * kk[j];
        }

        const int sbase = t * 64 + i0;
        const int zbase = kc * 64 + j0;
        #pragma unroll
        for (int i = 0; i < 4; i++)
            #pragma unroll
            for (int j = 0; j < 4; j++)
                if (zbase + j >= sbase + i) s_acc[i][j] = -1.0e12f;

        #pragma unroll
        for (int i = 0; i < 4; i++) {
            float mt = fmaxf(fmaxf(s_acc[i][0], s_acc[i][1]),
                             fmaxf(s_acc[i][2], s_acc[i][3]));
            #pragma unroll
            for (int o = 8; o > 0; o >>= 1)
                mt = fmaxf(mt, __shfl_xor_sync(0xffffffffu, mt, o, 16));
            const float mn = fmaxf(m[i], mt);
            const float sc = __expf(m[i] - mn);
            float ls = 0.f;
            #pragma unroll
            for (int j = 0; j < 4; j++) {
                s_acc[i][j] = __expf(s_acc[i][j] - mn);
                ls += s_acc[i][j];
            }
            #pragma unroll
            for (int o = 8; o > 0; o >>= 1)
                ls += __shfl_xor_sync(0xffffffffu, ls, o, 16);
            l[i] = l[i] * sc + ls;
            m[i] = mn;
            #pragma unroll
            for (int j = 0; j < 4; j++) o_acc[i][j] *= sc;
        }

        __syncthreads();
        float* Ps = Ks;
        #pragma unroll
        for (int i = 0; i < 4; i++)
            #pragma unroll
            for (int j = 0; j < 4; j++)
                Ps[(j0 + j) * 65 + (i0 + i)] = s_acc[i][j];
        __syncthreads();

        #pragma unroll 8
        for (int j = 0; j < 64; j++) {
            float p[4], v[4];
            #pragma unroll
            for (int i = 0; i < 4; i++) p[i] = Ps[j * 65 + i0 + i];
            *(float4*)&v[0] = *(float4*)&Vs[j * 64 + j0];
            #pragma unroll
            for (int i = 0; i < 4; i++)
                #pragma unroll
                for (int jj = 0; jj < 4; jj++)
                    o_acc[i][jj] += p[i] * v[jj];
        }
    }

    float* Og = O + ((size_t)b * Sseq + (size_t)t * 64) * Fdim + h * Dh;
    #pragma unroll
    for (int i = 0; i < 4; i++) {
        const float inv = 1.f / l[i];
        #pragma unroll
        for (int j = 0; j < 4; j++)
            Og[(size_t)(i0 + i) * Fdim + j0 + j] = o_acc[i][j] * inv;
    }
}

// ---------------------------------------------------------------------------
extern "C" void kernel_launch(void* const* d_in, const int* in_sizes, int n_in,
                              void* d_out, int out_size)
{
    (void)in_sizes; (void)n_in; (void)out_size;
    const float* attend_from = (const float*)d_in[0];
    const float* attend_to   = (const float*)d_in[1];
    const float* w_q   = (const float*)d_in[2];
    const float* b_q   = (const float*)d_in[3];
    const float* w_kv  = (const float*)d_in[4];
    const float* b_kv  = (const float*)d_in[5];
    const float* w_out = (const float*)d_in[6];
    const float* b_out = (const float*)d_in[7];
    float* out = (float*)d_out;

    float *Qp, *Kp, *Vp, *Op;
    cudaGetSymbolAddress((void**)&Qp, g_Q);
    cudaGetSymbolAddress((void**)&Kp, g_K);
    cudaGetSymbolAddress((void**)&Vp, g_V);
    cudaGetSymbolAddress((void**)&Op, g_O);

    const int flash_smem = (64 * 64 + 64 * 65 + 64 * 64) * (int)sizeof(float);
    cudaFuncSetAttribute(tf32_gemm_kernel<0>,
                         cudaFuncAttributeMaxDynamicSharedMemorySize, GEMM_SMEM);
    cudaFuncSetAttribute(tf32_gemm_kernel<1>,
                         cudaFuncAttributeMaxDynamicSharedMemorySize, GEMM_SMEM);
    cudaFuncSetAttribute(flash_kernel,
                         cudaFuncAttributeMaxDynamicSharedMemorySize, flash_smem);

    // 1) Q projection
    {
        dim3 grid(Fdim / 128, Mrows / 128);
        tf32_gemm_kernel<0><<<grid, 256, GEMM_SMEM>>>(
            attend_from, w_q, b_q, Qp, nullptr, Fdim, Fdim);
    }
    // 2) KV projection (split epilogue)
    {
        dim3 grid((2 * Fdim) / 128, Mrows / 128);
        tf32_gemm_kernel<1><<<grid, 256, GEMM_SMEM>>>(
            attend_to, w_kv, b_kv, Kp, Vp, Fdim, 2 * Fdim);
    }
    // 3) Fused masked attention
    {
        dim3 grid(Sseq / 64, Hh, Bsz);
        flash_kernel<<<grid, 256, flash_smem>>>(Qp, Kp, Vp, Op);
    }
    // 4) Output projection
    {
        dim3 grid(Fdim / 128, Mrows / 128);
        tf32_gemm_kernel<0><<<grid, 256, GEMM_SMEM>>>(
            Op, w_out, b_out, out, nullptr, Fdim, Fdim);
    }
}

// round 4
// speedup vs baseline: 1.4520x; 1.1970x over previous
#include <cuda_runtime.h>
#include <math.h>
#include <stdint.h>

// Problem constants (fixed shapes)
constexpr int Bsz  = 2;
constexpr int Sseq = 2048;
constexpr int Fdim = 1024;
constexpr int Hh   = 16;
constexpr int Dh   = 64;
constexpr int Mrows = Bsz * Sseq;   // 4096

// Scratch (allocation-free: device globals). 4 x 16MB.
__device__ float g_Q[(size_t)Mrows * Fdim];
__device__ float g_K[(size_t)Mrows * Fdim];
__device__ float g_V[(size_t)Mrows * Fdim];
__device__ float g_O[(size_t)Mrows * Fdim];

// ---------------------------------------------------------------------------
// Common PTX helpers
// ---------------------------------------------------------------------------
__device__ __forceinline__ void cp_async16(uint32_t saddr, const void* gptr) {
    asm volatile("cp.async.cg.shared.global [%0], [%1], 16;"
                 :: "r"(saddr), "l"(gptr));
}
__device__ __forceinline__ void cp_commit() {
    asm volatile("cp.async.commit_group;");
}
__device__ __forceinline__ void cp_wait0() {
    asm volatile("cp.async.wait_group 0;");
}
__device__ __forceinline__ void cp_wait1() {
    asm volatile("cp.async.wait_group 1;");
}

__device__ __forceinline__ uint32_t f2tf32(float x) {
    uint32_t r;
    asm("cvt.rna.tf32.f32 %0, %1;" : "=r"(r) : "f"(x));
    return r;
}

__device__ __forceinline__ void mma_tf32(
    float& d0, float& d1, float& d2, float& d3,
    uint32_t a0, uint32_t a1, uint32_t a2, uint32_t a3,
    uint32_t b0, uint32_t b1)
{
    asm volatile(
        "mma.sync.aligned.m16n8k8.row.col.f32.tf32.tf32.f32 "
        "{%0,%1,%2,%3},{%4,%5,%6,%7},{%8,%9},{%0,%1,%2,%3};"
        : "+f"(d0), "+f"(d1), "+f"(d2), "+f"(d3)
        : "r"(a0), "r"(a1), "r"(a2), "r"(a3), "r"(b0), "r"(b1));
}

// ---------------------------------------------------------------------------
// 3xTF32 tensor-core GEMM: C[M,N] = A[M,K] @ W[K,N] + bias[N]   (unchanged)
// ---------------------------------------------------------------------------
constexpr int SA = 36;
constexpr int SB = 132;
constexpr int AS_FLOATS = 128 * SA;
constexpr int BS_FLOATS = 32 * SB;
constexpr int STAGE_FLOATS = AS_FLOATS + BS_FLOATS;
constexpr int GEMM_SMEM = 2 * STAGE_FLOATS * 4;

template <int MODE>
__global__ __launch_bounds__(256) void tf32_gemm_kernel(
    const float* __restrict__ A, const float* __restrict__ W,
    const float* __restrict__ bias, float* __restrict__ C0,
    float* __restrict__ C1, int Kk, int Nn)
{
    extern __shared__ float sm[];
    const uint32_t sbase = (uint32_t)__cvta_generic_to_shared(sm);

    const int tid  = threadIdx.x;
    const int m0   = blockIdx.y * 128;
    const int n0   = blockIdx.x * 128;
    const int warp = tid >> 5;
    const int lane = tid & 31;
    const int wm   = warp & 1;
    const int wn   = warp >> 1;
    const int rbase = wm * 64;
    const int cbase = wn * 32;
    const int lr = lane >> 2;
    const int lc = lane & 3;

    float acc[4][4][4];
    #pragma unroll
    for (int i = 0; i < 4; i++)
        #pragma unroll
        for (int j = 0; j < 4; j++)
            #pragma unroll
            for (int r = 0; r < 4; r++) acc[i][j][r] = 0.f;

    auto load_tile = [&](int kt, int st) {
        const int k0 = kt * 32;
        const uint32_t sAa = sbase + (uint32_t)(st * STAGE_FLOATS) * 4u;
        const uint32_t sBb = sAa + (uint32_t)AS_FLOATS * 4u;
        #pragma unroll
        for (int r = 0; r < 4; r++) {
            const int slot = r * 256 + tid;
            const int row = slot >> 3, k4 = slot & 7;
            cp_async16(sAa + (uint32_t)(row * SA + k4 * 4) * 4u,
                       &A[(size_t)(m0 + row) * Kk + k0 + k4 * 4]);
        }
        #pragma unroll
        for (int r = 0; r < 4; r++) {
            const int slot = r * 256 + tid;
            const int k = slot >> 5, n4 = slot & 31;
            cp_async16(sBb + (uint32_t)(k * SB + n4 * 4) * 4u,
                       &W[(size_t)(k0 + k) * Nn + n0 + n4 * 4]);
        }
    };

    const int NT = Kk / 32;
    load_tile(0, 0);
    cp_commit();

    for (int kt = 0; kt < NT; kt++) {
        cp_wait0();
        __syncthreads();
        if (kt + 1 < NT) { load_tile(kt + 1, (kt + 1) & 1); cp_commit(); }

        const float* As = sm + (kt & 1) * STAGE_FLOATS;
        const float* Bs = As + AS_FLOATS;

        #pragma unroll
        for (int ks = 0; ks < 4; ks++) {
            const int kk = ks * 8;
            uint32_t ah[4][4], al[4][4], bh[4][2], bl[4][2];
            #pragma unroll
            for (int mi = 0; mi < 4; mi++) {
                const int rr = rbase + mi * 16 + lr;
                float v0 = As[rr * SA + kk + lc];
                float v1 = As[(rr + 8) * SA + kk + lc];
                float v2 = As[rr * SA + kk + lc + 4];
                float v3 = As[(rr + 8) * SA + kk + lc + 4];
                ah[mi][0] = f2tf32(v0); al[mi][0] = __float_as_uint(v0 - __uint_as_float(ah[mi][0]));
                ah[mi][1] = f2tf32(v1); al[mi][1] = __float_as_uint(v1 - __uint_as_float(ah[mi][1]));
                ah[mi][2] = f2tf32(v2); al[mi][2] = __float_as_uint(v2 - __uint_as_float(ah[mi][2]));
                ah[mi][3] = f2tf32(v3); al[mi][3] = __float_as_uint(v3 - __uint_as_float(ah[mi][3]));
            }
            #pragma unroll
            for (int nj = 0; nj < 4; nj++) {
                const int cc = cbase + nj * 8 + lr;
                float w0 = Bs[(kk + lc) * SB + cc];
                float w1 = Bs[(kk + lc + 4) * SB + cc];
                bh[nj][0] = f2tf32(w0); bl[nj][0] = __float_as_uint(w0 - __uint_as_float(bh[nj][0]));
                bh[nj][1] = f2tf32(w1); bl[nj][1] = __float_as_uint(w1 - __uint_as_float(bh[nj][1]));
            }
            #pragma unroll
            for (int mi = 0; mi < 4; mi++)
                #pragma unroll
                for (int nj = 0; nj < 4; nj++) {
                    mma_tf32(acc[mi][nj][0], acc[mi][nj][1],
                             acc[mi][nj][2], acc[mi][nj][3],
                             al[mi][0], al[mi][1], al[mi][2], al[mi][3],
                             bh[nj][0], bh[nj][1]);
                    mma_tf32(acc[mi][nj][0], acc[mi][nj][1],
                             acc[mi][nj][2], acc[mi][nj][3],
                             ah[mi][0], ah[mi][1], ah[mi][2], ah[mi][3],
                             bl[nj][0], bl[nj][1]);
                    mma_tf32(acc[mi][nj][0], acc[mi][nj][1],
                             acc[mi][nj][2], acc[mi][nj][3],
                             ah[mi][0], ah[mi][1], ah[mi][2], ah[mi][3],
                             bh[nj][0], bh[nj][1]);
                }
        }
        __syncthreads();
    }

    float* Cb;
    int nshift;
    if (MODE == 0) { Cb = C0; nshift = 0; }
    else if (n0 < 1024) { Cb = C0; nshift = 0; }
    else { Cb = C1; nshift = 1024; }
    const int ldc = (MODE == 0) ? Nn : 1024;

    #pragma unroll
    for (int mi = 0; mi < 4; mi++) {
        const int row = m0 + rbase + mi * 16 + lr;
        #pragma unroll
        for (int nj = 0; nj < 4; nj++) {
            const int col = n0 + cbase + nj * 8 + lc * 2;
            const float bx = bias[col], by = bias[col + 1];
            float2 v0 = make_float2(acc[mi][nj][0] + bx, acc[mi][nj][1] + by);
            float2 v1 = make_float2(acc[mi][nj][2] + bx, acc[mi][nj][3] + by);
            *(float2*)&Cb[(size_t)row * ldc + col - nshift] = v0;
            *(float2*)&Cb[(size_t)(row + 8) * ldc + col - nshift] = v1;
        }
    }
}

// ---------------------------------------------------------------------------
// Tensor-core flash attention (3xTF32), Br=128, Bc=64, d=64.
// 8 warps; warp w owns q-rows 16w..16w+15 (softmax stats warp-local).
// Q fragments in registers (tf32 hi/lo); K/V cp.async double-buffered;
// P staged through per-warp smem stripe. Mask: z >= s -> logit -1e12f.
// CTA t covers rows 128t..128t+127; iterates 2t+2 kv tiles (t=0: all 32,
// so fully-masked row 0 is a uniform softmax over all 2048 keys).
// ---------------------------------------------------------------------------
constexpr int KST = 68;                  // Ks stride (banks: l/4*4+l%4 distinct)
constexpr int VST = 72;                  // Vs stride (banks: l%4*8+l/4 distinct)
constexpr int PST = 68;                  // Ps / Q-staging stride
constexpr int KS_FLOATS = 64 * KST;      // 4352
constexpr int VS_FLOATS = 64 * VST;      // 4608
constexpr int PS_FLOATS = 128 * PST;     // 8704
constexpr int PS_OFF    = 2 * KS_FLOATS + 2 * VS_FLOATS;
constexpr int FLASH_SMEM = (PS_OFF + PS_FLOATS) * 4;   // 106496 B

__global__ __launch_bounds__(256) void flash_mma_kernel(
    const float* __restrict__ Q, const float* __restrict__ K,
    const float* __restrict__ V, float* __restrict__ O)
{
    extern __shared__ float sm[];
    const uint32_t sbase = (uint32_t)__cvta_generic_to_shared(sm);
    float* Ps = sm + PS_OFF;

    const int x = blockIdx.x;
    const int t = (x == 0) ? 0 : (16 - x);       // heavy CTAs first
    const int h = blockIdx.y;
    const int b = blockIdx.z;
    const int tid  = threadIdx.x;
    const int warp = tid >> 5;
    const int lane = tid & 31;
    const int lq  = lane >> 2;                   // 0..7 (row within 8-group)
    const int lr4 = lane & 3;                    // 0..3

    const float* Qg = Q + ((size_t)b * Sseq + (size_t)t * 128) * Fdim + h * Dh;
    const float* Kg = K + ((size_t)b * Sseq) * Fdim + h * Dh;
    const float* Vg = V + ((size_t)b * Sseq) * Fdim + h * Dh;

    // Stage Q (128x64) into Ps region via cp.async (group 0)
    #pragma unroll
    for (int r = 0; r < 8; r++) {
        const int slot = r * 256 + tid;
        const int row = slot >> 4;
        const int c4 = slot & 15;
        cp_async16(sbase + (uint32_t)(PS_OFF + row * PST + c4 * 4) * 4u,
                   &Qg[(size_t)row * Fdim + c4 * 4]);
    }
    cp_commit();

    auto load_kv = [&](int kc, int st) {
        const float* Kgk = Kg + (size_t)(kc * 64) * Fdim;
        const float* Vgk = Vg + (size_t)(kc * 64) * Fdim;
        const uint32_t kd = sbase + (uint32_t)(st * KS_FLOATS) * 4u;
        const uint32_t vd = sbase + (uint32_t)(2 * KS_FLOATS + st * VS_FLOATS) * 4u;
        #pragma unroll
        for (int r = 0; r < 4; r++) {
            const int slot = r * 256 + tid;
            const int row = slot >> 4;
            const int c4 = slot & 15;
            cp_async16(kd + (uint32_t)(row * KST + c4 * 4) * 4u,
                       &Kgk[(size_t)row * Fdim + c4 * 4]);
            cp_async16(vd + (uint32_t)(row * VST + c4 * 4) * 4u,
                       &Vgk[(size_t)row * Fdim + c4 * 4]);
        }
    };

    load_kv(0, 0);           // group 1
    cp_commit();

    cp_wait1();              // Q staged
    __syncthreads();

    // Extract Q fragments (warp-private rows) -> tf32 hi/lo registers
    uint32_t qh[8][4], ql[8][4];
    {
        const float* Pw = Ps + warp * 16 * PST;
        #pragma unroll
        for (int kk = 0; kk < 8; kk++) {
            const int c = kk * 8 + lr4;
            float v0 = Pw[lq * PST + c];
            float v1 = Pw[(lq + 8) * PST + c];
            float v2 = Pw[lq * PST + c + 4];
            float v3 = Pw[(lq + 8) * PST + c + 4];
            qh[kk][0] = f2tf32(v0); ql[kk][0] = __float_as_uint(v0 - __uint_as_float(qh[kk][0]));
            qh[kk][1] = f2tf32(v1); ql[kk][1] = __float_as_uint(v1 - __uint_as_float(qh[kk][1]));
            qh[kk][2] = f2tf32(v2); ql[kk][2] = __float_as_uint(v2 - __uint_as_float(qh[kk][2]));
            qh[kk][3] = f2tf32(v3); ql[kk][3] = __float_as_uint(v3 - __uint_as_float(qh[kk][3]));
        }
    }

    float oacc[8][4];
    #pragma unroll
    for (int nt = 0; nt < 8; nt++)
        #pragma unroll
        for (int r = 0; r < 4; r++) oacc[nt][r] = 0.f;
    float m0 = -3.0e38f, m1 = -3.0e38f, l0 = 0.f, l1 = 0.f;

    const int row0 = t * 128 + warp * 16 + lq;
    const int row1 = row0 + 8;
    const int nkc = (t == 0) ? (Sseq / 64) : (2 * t + 2);

    for (int kc = 0; kc < nkc; kc++) {
        cp_wait0();
        __syncthreads();
        if (kc + 1 < nkc) { load_kv(kc + 1, (kc + 1) & 1); cp_commit(); }

        const float* Kt = sm + (kc & 1) * KS_FLOATS;
        const float* Vt = sm + 2 * KS_FLOATS + (kc & 1) * VS_FLOATS;

        // ---- S = Q @ K^T (16x64 per warp) ----
        float sacc[8][4];
        #pragma unroll
        for (int nt = 0; nt < 8; nt++)
            #pragma unroll
            for (int r = 0; r < 4; r++) sacc[nt][r] = 0.f;

        #pragma unroll
        for (int kk = 0; kk < 8; kk++) {
            uint32_t bh[8][2], bl[8][2];
            #pragma unroll
            for (int nt = 0; nt < 8; nt++) {
                const int krow = nt * 8 + lq;
                float w0 = Kt[krow * KST + kk * 8 + lr4];
                float w1 = Kt[krow * KST + kk * 8 + lr4 + 4];
                bh[nt][0] = f2tf32(w0); bl[nt][0] = __float_as_uint(w0 - __uint_as_float(bh[nt][0]));
                bh[nt][1] = f2tf32(w1); bl[nt][1] = __float_as_uint(w1 - __uint_as_float(bh[nt][1]));
            }
            #pragma unroll
            for (int nt = 0; nt < 8; nt++) {
                mma_tf32(sacc[nt][0], sacc[nt][1], sacc[nt][2], sacc[nt][3],
                         ql[kk][0], ql[kk][1], ql[kk][2], ql[kk][3],
                         bh[nt][0], bh[nt][1]);
                mma_tf32(sacc[nt][0], sacc[nt][1], sacc[nt][2], sacc[nt][3],
                         qh[kk][0], qh[kk][1], qh[kk][2], qh[kk][3],
                         bl[nt][0], bl[nt][1]);
                mma_tf32(sacc[nt][0], sacc[nt][1], sacc[nt][2], sacc[nt][3],
                         qh[kk][0], qh[kk][1], qh[kk][2], qh[kk][3],
                         bh[nt][0], bh[nt][1]);
            }
        }

        // ---- mask: z >= s -> -1e12 ----
        #pragma unroll
        for (int nt = 0; nt < 8; nt++) {
            const int cb = kc * 64 + nt * 8 + 2 * lr4;
            if (cb     >= row0) sacc[nt][0] = -1.0e12f;
            if (cb + 1 >= row0) sacc[nt][1] = -1.0e12f;
            if (cb     >= row1) sacc[nt][2] = -1.0e12f;
            if (cb + 1 >= row1) sacc[nt][3] = -1.0e12f;
        }

        // ---- online softmax (rows row0, row1; stats across 4 quad lanes) ----
        float mt0 = -3.0e38f, mt1 = -3.0e38f;
        #pragma unroll
        for (int nt = 0; nt < 8; nt++) {
            mt0 = fmaxf(mt0, fmaxf(sacc[nt][0], sacc[nt][1]));
            mt1 = fmaxf(mt1, fmaxf(sacc[nt][2], sacc[nt][3]));
        }
        mt0 = fmaxf(mt0, __shfl_xor_sync(0xffffffffu, mt0, 1));
        mt0 = fmaxf(mt0, __shfl_xor_sync(0xffffffffu, mt0, 2));
        mt1 = fmaxf(mt1, __shfl_xor_sync(0xffffffffu, mt1, 1));
        mt1 = fmaxf(mt1, __shfl_xor_sync(0xffffffffu, mt1, 2));
        const float mn0 = fmaxf(m0, mt0);
        const float mn1 = fmaxf(m1, mt1);
        const float sc0 = __expf(m0 - mn0);
        const float sc1 = __expf(m1 - mn1);
        float ls0 = 0.f, ls1 = 0.f;
        #pragma unroll
        for (int nt = 0; nt < 8; nt++) {
            sacc[nt][0] = __expf(sacc[nt][0] - mn0);
            sacc[nt][1] = __expf(sacc[nt][1] - mn0);
            sacc[nt][2] = __expf(sacc[nt][2] - mn1);
            sacc[nt][3] = __expf(sacc[nt][3] - mn1);
            ls0 += sacc[nt][0] + sacc[nt][1];
            ls1 += sacc[nt][2] + sacc[nt][3];
        }
        l0 = l0 * sc0 + ls0;
        l1 = l1 * sc1 + ls1;
        m0 = mn0; m1 = mn1;
        #pragma unroll
        for (int nt = 0; nt < 8; nt++) {
            oacc[nt][0] *= sc0; oacc[nt][1] *= sc0;
            oacc[nt][2] *= sc1; oacc[nt][3] *= sc1;
        }

        // ---- stage P in per-warp smem stripe ----
        float* Pw = Ps + warp * 16 * PST;
        #pragma unroll
        for (int nt = 0; nt < 8; nt++) {
            *(float2*)&Pw[lq * PST + nt * 8 + 2 * lr4] =
                make_float2(sacc[nt][0], sacc[nt][1]);
            *(float2*)&Pw[(lq + 8) * PST + nt * 8 + 2 * lr4] =
                make_float2(sacc[nt][2], sacc[nt][3]);
        }
        __syncwarp();

        // ---- O += P @ V ----
        #pragma unroll
        for (int kk = 0; kk < 8; kk++) {
            const int c = kk * 8 + lr4;
            float p0 = Pw[lq * PST + c];
            float p1 = Pw[(lq + 8) * PST + c];
            float p2 = Pw[lq * PST + c + 4];
            float p3 = Pw[(lq + 8) * PST + c + 4];
            uint32_t ph[4], pl[4];
            ph[0] = f2tf32(p0); pl[0] = __float_as_uint(p0 - __uint_as_float(ph[0]));
            ph[1] = f2tf32(p1); pl[1] = __float_as_uint(p1 - __uint_as_float(ph[1]));
            ph[2] = f2tf32(p2); pl[2] = __float_as_uint(p2 - __uint_as_float(ph[2]));
            ph[3] = f2tf32(p3); pl[3] = __float_as_uint(p3 - __uint_as_float(ph[3]));
            #pragma unroll
            for (int nt = 0; nt < 8; nt++) {
                float w0 = Vt[(kk * 8 + lr4) * VST + nt * 8 + lq];
                float w1 = Vt[(kk * 8 + lr4 + 4) * VST + nt * 8 + lq];
                uint32_t vh0 = f2tf32(w0);
                uint32_t vl0 = __float_as_uint(w0 - __uint_as_float(vh0));
                uint32_t vh1 = f2tf32(w1);
                uint32_t vl1 = __float_as_uint(w1 - __uint_as_float(vh1));
                mma_tf32(oacc[nt][0], oacc[nt][1], oacc[nt][2], oacc[nt][3],
                         pl[0], pl[1], pl[2], pl[3], vh0, vh1);
                mma_tf32(oacc[nt][0], oacc[nt][1], oacc[nt][2], oacc[nt][3],
                         ph[0], ph[1], ph[2], ph[3], vl0, vl1);
                mma_tf32(oacc[nt][0], oacc[nt][1], oacc[nt][2], oacc[nt][3],
                         ph[0], ph[1], ph[2], ph[3], vh0, vh1);
            }
        }
        __syncwarp();
    }

    // ---- epilogue: normalize by row sums and store ----
    l0 += __shfl_xor_sync(0xffffffffu, l0, 1);
    l0 += __shfl_xor_sync(0xffffffffu, l0, 2);
    l1 += __shfl_xor_sync(0xffffffffu, l1, 1);
    l1 += __shfl_xor_sync(0xffffffffu, l1, 2);
    const float inv0 = 1.f / l0;
    const float inv1 = 1.f / l1;

    float* Og = O + ((size_t)b * Sseq + (size_t)t * 128 + warp * 16) * Fdim + h * Dh;
    #pragma unroll
    for (int nt = 0; nt < 8; nt++) {
        const int cb = nt * 8 + 2 * lr4;
        *(float2*)&Og[(size_t)lq * Fdim + cb] =
            make_float2(oacc[nt][0] * inv0, oacc[nt][1] * inv0);
        *(float2*)&Og[(size_t)(lq + 8) * Fdim + cb] =
            make_float2(oacc[nt][2] * inv1, oacc[nt][3] * inv1);
    }
}

// ---------------------------------------------------------------------------
extern "C" void kernel_launch(void* const* d_in, const int* in_sizes, int n_in,
                              void* d_out, int out_size)
{
    (void)in_sizes; (void)n_in; (void)out_size;
    const float* attend_from = (const float*)d_in[0];
    const float* attend_to   = (const float*)d_in[1];
    const float* w_q   = (const float*)d_in[2];
    const float* b_q   = (const float*)d_in[3];
    const float* w_kv  = (const float*)d_in[4];
    const float* b_kv  = (const float*)d_in[5];
    const float* w_out = (const float*)d_in[6];
    const float* b_out = (const float*)d_in[7];
    float* out = (float*)d_out;

    float *Qp, *Kp, *Vp, *Op;
    cudaGetSymbolAddress((void**)&Qp, g_Q);
    cudaGetSymbolAddress((void**)&Kp, g_K);
    cudaGetSymbolAddress((void**)&Vp, g_V);
    cudaGetSymbolAddress((void**)&Op, g_O);

    cudaFuncSetAttribute(tf32_gemm_kernel<0>,
                         cudaFuncAttributeMaxDynamicSharedMemorySize, GEMM_SMEM);
    cudaFuncSetAttribute(tf32_gemm_kernel<1>,
                         cudaFuncAttributeMaxDynamicSharedMemorySize, GEMM_SMEM);
    cudaFuncSetAttribute(flash_mma_kernel,
                         cudaFuncAttributeMaxDynamicSharedMemorySize, FLASH_SMEM);

    // 1) Q projection
    {
        dim3 grid(Fdim / 128, Mrows / 128);
        tf32_gemm_kernel<0><<<grid, 256, GEMM_SMEM>>>(
            attend_from, w_q, b_q, Qp, nullptr, Fdim, Fdim);
    }
    // 2) KV projection (split epilogue)
    {
        dim3 grid((2 * Fdim) / 128, Mrows / 128);
        tf32_gemm_kernel<1><<<grid, 256, GEMM_SMEM>>>(
            attend_to, w_kv, b_kv, Kp, Vp, Fdim, 2 * Fdim);
    }
    // 3) Tensor-core flash attention
    {
        dim3 grid(Sseq / 128, Hh, Bsz);
        flash_mma_kernel<<<grid, 256, FLASH_SMEM>>>(Qp, Kp, Vp, Op);
    }
    // 4) Output projection
    {
        dim3 grid(Fdim / 128, Mrows / 128);
        tf32_gemm_kernel<0><<<grid, 256, GEMM_SMEM>>>(
            Op, w_out, b_out, out, nullptr, Fdim, Fdim);
    }
}

// round 5
// speedup vs baseline: 1.5322x; 1.0552x over previous
#include <cuda_runtime.h>
#include <math.h>
#include <stdint.h>

// Problem constants (fixed shapes)
constexpr int Bsz  = 2;
constexpr int Sseq = 2048;
constexpr int Fdim = 1024;
constexpr int Hh   = 16;
constexpr int Dh   = 64;
constexpr int Mrows = Bsz * Sseq;   // 4096

// Scratch (allocation-free: device globals). Q/K/V stored pre-split into
// tf32 hi (rna-rounded fp32 bits) and lo (residual fp32) arrays.
__device__ float g_Qhi[(size_t)Mrows * Fdim];
__device__ float g_Qlo[(size_t)Mrows * Fdim];
__device__ float g_Khi[(size_t)Mrows * Fdim];
__device__ float g_Klo[(size_t)Mrows * Fdim];
__device__ float g_Vhi[(size_t)Mrows * Fdim];
__device__ float g_Vlo[(size_t)Mrows * Fdim];
__device__ float g_O  [(size_t)Mrows * Fdim];

// ---------------------------------------------------------------------------
// Common PTX helpers
// ---------------------------------------------------------------------------
__device__ __forceinline__ void cp_async16(uint32_t saddr, const void* gptr) {
    asm volatile("cp.async.cg.shared.global [%0], [%1], 16;"
                 :: "r"(saddr), "l"(gptr));
}
__device__ __forceinline__ void cp_commit() {
    asm volatile("cp.async.commit_group;");
}
__device__ __forceinline__ void cp_wait0() {
    asm volatile("cp.async.wait_group 0;");
}
__device__ __forceinline__ void cp_wait1() {
    asm volatile("cp.async.wait_group 1;");
}

__device__ __forceinline__ uint32_t f2tf32(float x) {
    uint32_t r;
    asm("cvt.rna.tf32.f32 %0, %1;" : "=r"(r) : "f"(x));
    return r;
}

__device__ __forceinline__ void mma_tf32(
    float& d0, float& d1, float& d2, float& d3,
    uint32_t a0, uint32_t a1, uint32_t a2, uint32_t a3,
    uint32_t b0, uint32_t b1)
{
    asm volatile(
        "mma.sync.aligned.m16n8k8.row.col.f32.tf32.tf32.f32 "
        "{%0,%1,%2,%3},{%4,%5,%6,%7},{%8,%9},{%0,%1,%2,%3};"
        : "+f"(d0), "+f"(d1), "+f"(d2), "+f"(d3)
        : "r"(a0), "r"(a1), "r"(a2), "r"(a3), "r"(b0), "r"(b1));
}

// ---------------------------------------------------------------------------
// 3xTF32 GEMM core (128x128 tile, BK=32, 8 warps of 64x32, cp.async x2).
// ---------------------------------------------------------------------------
constexpr int SA = 36;
constexpr int SB = 132;
constexpr int AS_FLOATS = 128 * SA;
constexpr int BS_FLOATS = 32 * SB;
constexpr int STAGE_FLOATS = AS_FLOATS + BS_FLOATS;
constexpr int GEMM_SMEM = 2 * STAGE_FLOATS * 4;

// Shared mainloop: returns 64 accumulators for this thread's warp tile.
struct GemmCore {
    float acc[4][4][4];
};

template <typename EPI>
__device__ __forceinline__ void gemm_mainloop(
    const float* __restrict__ A, const float* __restrict__ W,
    int m0, int n0, int Kk, int Nn, float* sm, EPI epi)
{
    const uint32_t sbase = (uint32_t)__cvta_generic_to_shared(sm);
    const int tid  = threadIdx.x;
    const int warp = tid >> 5;
    const int lane = tid & 31;
    const int wm   = warp & 1;
    const int wn   = warp >> 1;
    const int rbase = wm * 64;
    const int cbase = wn * 32;
    const int lr = lane >> 2;
    const int lc = lane & 3;

    float acc[4][4][4];
    #pragma unroll
    for (int i = 0; i < 4; i++)
        #pragma unroll
        for (int j = 0; j < 4; j++)
            #pragma unroll
            for (int r = 0; r < 4; r++) acc[i][j][r] = 0.f;

    auto load_tile = [&](int kt, int st) {
        const int k0 = kt * 32;
        const uint32_t sAa = sbase + (uint32_t)(st * STAGE_FLOATS) * 4u;
        const uint32_t sBb = sAa + (uint32_t)AS_FLOATS * 4u;
        #pragma unroll
        for (int r = 0; r < 4; r++) {
            const int slot = r * 256 + tid;
            const int row = slot >> 3, k4 = slot & 7;
            cp_async16(sAa + (uint32_t)(row * SA + k4 * 4) * 4u,
                       &A[(size_t)(m0 + row) * Kk + k0 + k4 * 4]);
        }
        #pragma unroll
        for (int r = 0; r < 4; r++) {
            const int slot = r * 256 + tid;
            const int k = slot >> 5, n4 = slot & 31;
            cp_async16(sBb + (uint32_t)(k * SB + n4 * 4) * 4u,
                       &W[(size_t)(k0 + k) * Nn + n0 + n4 * 4]);
        }
    };

    const int NT = Kk / 32;
    load_tile(0, 0);
    cp_commit();

    for (int kt = 0; kt < NT; kt++) {
        cp_wait0();
        __syncthreads();
        if (kt + 1 < NT) { load_tile(kt + 1, (kt + 1) & 1); cp_commit(); }

        const float* As = sm + (kt & 1) * STAGE_FLOATS;
        const float* Bs = As + AS_FLOATS;

        #pragma unroll
        for (int ks = 0; ks < 4; ks++) {
            const int kk = ks * 8;
            uint32_t ah[4][4], al[4][4], bh[4][2], bl[4][2];
            #pragma unroll
            for (int mi = 0; mi < 4; mi++) {
                const int rr = rbase + mi * 16 + lr;
                float v0 = As[rr * SA + kk + lc];
                float v1 = As[(rr + 8) * SA + kk + lc];
                float v2 = As[rr * SA + kk + lc + 4];
                float v3 = As[(rr + 8) * SA + kk + lc + 4];
                ah[mi][0] = f2tf32(v0); al[mi][0] = __float_as_uint(v0 - __uint_as_float(ah[mi][0]));
                ah[mi][1] = f2tf32(v1); al[mi][1] = __float_as_uint(v1 - __uint_as_float(ah[mi][1]));
                ah[mi][2] = f2tf32(v2); al[mi][2] = __float_as_uint(v2 - __uint_as_float(ah[mi][2]));
                ah[mi][3] = f2tf32(v3); al[mi][3] = __float_as_uint(v3 - __uint_as_float(ah[mi][3]));
            }
            #pragma unroll
            for (int nj = 0; nj < 4; nj++) {
                const int cc = cbase + nj * 8 + lr;
                float w0 = Bs[(kk + lc) * SB + cc];
                float w1 = Bs[(kk + lc + 4) * SB + cc];
                bh[nj][0] = f2tf32(w0); bl[nj][0] = __float_as_uint(w0 - __uint_as_float(bh[nj][0]));
                bh[nj][1] = f2tf32(w1); bl[nj][1] = __float_as_uint(w1 - __uint_as_float(bh[nj][1]));
            }
            #pragma unroll
            for (int mi = 0; mi < 4; mi++)
                #pragma unroll
                for (int nj = 0; nj < 4; nj++) {
                    mma_tf32(acc[mi][nj][0], acc[mi][nj][1],
                             acc[mi][nj][2], acc[mi][nj][3],
                             al[mi][0], al[mi][1], al[mi][2], al[mi][3],
                             bh[nj][0], bh[nj][1]);
                    mma_tf32(acc[mi][nj][0], acc[mi][nj][1],
                             acc[mi][nj][2], acc[mi][nj][3],
                             ah[mi][0], ah[mi][1], ah[mi][2], ah[mi][3],
                             bl[nj][0], bl[nj][1]);
                    mma_tf32(acc[mi][nj][0], acc[mi][nj][1],
                             acc[mi][nj][2], acc[mi][nj][3],
                             ah[mi][0], ah[mi][1], ah[mi][2], ah[mi][3],
                             bh[nj][0], bh[nj][1]);
                }
        }
        __syncthreads();
    }

    epi(acc, rbase, cbase, lr, lc);
}

// Merged Q + KV projection: grid.x = 768.
//   bx <  256: Q  = attend_from @ w_q  + b_q  -> (g_Qhi, g_Qlo)
//   bx >= 256: KV = attend_to   @ w_kv + b_kv -> (g_Khi,g_Klo) | (g_Vhi,g_Vlo)
__global__ __launch_bounds__(256) void qkv_gemm_kernel(
    const float* __restrict__ Xq, const float* __restrict__ Xkv,
    const float* __restrict__ Wq, const float* __restrict__ Wkv,
    const float* __restrict__ bq, const float* __restrict__ bkv,
    float* __restrict__ Qhi, float* __restrict__ Qlo,
    float* __restrict__ Khi, float* __restrict__ Klo,
    float* __restrict__ Vhi, float* __restrict__ Vlo)
{
    extern __shared__ float sm[];
    const int bx = blockIdx.x;

    const float *A, *W, *bias;
    float *Dhi, *Dlo;
    int m0, n0, Nn, ncol;
    if (bx < 256) {
        A = Xq; W = Wq; bias = bq; Nn = 1024;
        m0 = (bx >> 3) * 128; n0 = (bx & 7) * 128;
        Dhi = Qhi; Dlo = Qlo; ncol = n0;
    } else {
        const int bxx = bx - 256;
        A = Xkv; W = Wkv; bias = bkv; Nn = 2048;
        m0 = (bxx >> 4) * 128; n0 = (bxx & 15) * 128;
        if (n0 < 1024) { Dhi = Khi; Dlo = Klo; ncol = n0; }
        else           { Dhi = Vhi; Dlo = Vlo; ncol = n0 - 1024; }
    }

    gemm_mainloop(A, W, m0, n0, Fdim, Nn, sm,
        [&](float (&acc)[4][4][4], int rbase, int cbase, int lr, int lc) {
            #pragma unroll
            for (int mi = 0; mi < 4; mi++) {
                const int row = m0 + rbase + mi * 16 + lr;
                #pragma unroll
                for (int nj = 0; nj < 4; nj++) {
                    const int col = ncol + cbase + nj * 8 + lc * 2;
                    const float bx0 = bias[n0 - ncol + col];
                    const float bx1 = bias[n0 - ncol + col + 1];
                    float v00 = acc[mi][nj][0] + bx0;
                    float v01 = acc[mi][nj][1] + bx1;
                    float v10 = acc[mi][nj][2] + bx0;
                    float v11 = acc[mi][nj][3] + bx1;
                    uint32_t h00 = f2tf32(v00), h01 = f2tf32(v01);
                    uint32_t h10 = f2tf32(v10), h11 = f2tf32(v11);
                    const size_t o0 = (size_t)row * 1024 + col;
                    const size_t o1 = (size_t)(row + 8) * 1024 + col;
                    *(float2*)&Dhi[o0] = make_float2(__uint_as_float(h00), __uint_as_float(h01));
                    *(float2*)&Dhi[o1] = make_float2(__uint_as_float(h10), __uint_as_float(h11));
                    *(float2*)&Dlo[o0] = make_float2(v00 - __uint_as_float(h00), v01 - __uint_as_float(h01));
                    *(float2*)&Dlo[o1] = make_float2(v10 - __uint_as_float(h10), v11 - __uint_as_float(h11));
                }
            }
        });
}

// Output projection: out = O @ w_out + b_out (plain fp32 store).
__global__ __launch_bounds__(256) void out_gemm_kernel(
    const float* __restrict__ A, const float* __restrict__ W,
    const float* __restrict__ bias, float* __restrict__ C)
{
    extern __shared__ float sm[];
    const int m0 = blockIdx.y * 128;
    const int n0 = blockIdx.x * 128;
    gemm_mainloop(A, W, m0, n0, Fdim, Fdim, sm,
        [&](float (&acc)[4][4][4], int rbase, int cbase, int lr, int lc) {
            #pragma unroll
            for (int mi = 0; mi < 4; mi++) {
                const int row = m0 + rbase + mi * 16 + lr;
                #pragma unroll
                for (int nj = 0; nj < 4; nj++) {
                    const int col = n0 + cbase + nj * 8 + lc * 2;
                    const float bx = bias[col], by = bias[col + 1];
                    *(float2*)&C[(size_t)row * Fdim + col] =
                        make_float2(acc[mi][nj][0] + bx, acc[mi][nj][1] + by);
                    *(float2*)&C[(size_t)(row + 8) * Fdim + col] =
                        make_float2(acc[mi][nj][2] + bx, acc[mi][nj][3] + by);
                }
            }
        });
}

// ---------------------------------------------------------------------------
// Tensor-core flash attention, pre-split operands. Br=128, Bc=64, d=64.
// K/V arrive as (hi,lo) tiles via cp.async -> zero cvt/sub in the hot loop.
// S = 3 MMAs (ql*bh + qh*bl + qh*bh). O += 2 MMAs (ph*vl + ph*vh); the
// P_lo*V term is dropped (expected contribution ~1e-4 rel, budget 1e-3).
// Mask: z >= s -> logit -1e12f; CTA t iterates 2t+2 kv tiles (t=0: all 32).
// ---------------------------------------------------------------------------
constexpr int KST = 68;
constexpr int VST = 72;
constexpr int PST = 68;
constexpr int KTILE = 64 * KST;          // 4352
constexpr int VTILE = 64 * VST;          // 4608
constexpr int KHI_OFF = 0;
constexpr int KLO_OFF = 2 * KTILE;       // 8704
constexpr int VHI_OFF = 4 * KTILE;       // 17408
constexpr int VLO_OFF = VHI_OFF + 2 * VTILE;  // 26624
constexpr int PS_OFF  = VLO_OFF + 2 * VTILE;  // 35840
constexpr int FLASH_FLOATS = PS_OFF + 128 * PST;  // 44544
constexpr int FLASH_SMEM = FLASH_FLOATS * 4;      // 178176 B

__global__ __launch_bounds__(256) void flash_mma_kernel(
    const float* __restrict__ Qhi, const float* __restrict__ Qlo,
    const float* __restrict__ Khi, const float* __restrict__ Klo,
    const float* __restrict__ Vhi, const float* __restrict__ Vlo,
    float* __restrict__ O)
{
    extern __shared__ float sm[];
    const uint32_t sbase = (uint32_t)__cvta_generic_to_shared(sm);
    float* Ps = sm + PS_OFF;

    const int x = blockIdx.x;
    const int t = (x == 0) ? 0 : (16 - x);       // heavy CTAs first
    const int h = blockIdx.y;
    const int b = blockIdx.z;
    const int tid  = threadIdx.x;
    const int warp = tid >> 5;
    const int lane = tid & 31;
    const int lq  = lane >> 2;
    const int lr4 = lane & 3;

    const size_t qoff = ((size_t)b * Sseq + (size_t)t * 128) * Fdim + h * Dh;
    const size_t koff = ((size_t)b * Sseq) * Fdim + h * Dh;

    auto load_kv = [&](int kc, int st) {
        const size_t base = koff + (size_t)(kc * 64) * Fdim;
        const uint32_t khd = sbase + (uint32_t)(KHI_OFF + st * KTILE) * 4u;
        const uint32_t kld = sbase + (uint32_t)(KLO_OFF + st * KTILE) * 4u;
        const uint32_t vhd = sbase + (uint32_t)(VHI_OFF + st * VTILE) * 4u;
        const uint32_t vld = sbase + (uint32_t)(VLO_OFF + st * VTILE) * 4u;
        #pragma unroll
        for (int r = 0; r < 4; r++) {
            const int slot = r * 256 + tid;
            const int row = slot >> 4;
            const int c4 = (slot & 15) * 4;
            const size_t g = base + (size_t)row * Fdim + c4;
            const uint32_t ks = (uint32_t)(row * KST + c4) * 4u;
            const uint32_t vs = (uint32_t)(row * VST + c4) * 4u;
            cp_async16(khd + ks, &Khi[g]);
            cp_async16(kld + ks, &Klo[g]);
            cp_async16(vhd + vs, &Vhi[g]);
            cp_async16(vld + vs, &Vlo[g]);
        }
    };

    auto stage_q = [&](const float* src) {
        #pragma unroll
        for (int r = 0; r < 8; r++) {
            const int slot = r * 256 + tid;
            const int row = slot >> 4;
            const int c4 = (slot & 15) * 4;
            cp_async16(sbase + (uint32_t)(PS_OFF + row * PST + c4) * 4u,
                       &src[qoff + (size_t)row * Fdim + c4]);
        }
    };

    // Pipeline warm-up: qhi (g0), kv0 (g1), then qlo (g2).
    stage_q(Qhi); cp_commit();
    load_kv(0, 0); cp_commit();

    uint32_t qh[8][4], ql[8][4];
    const float* Pw = Ps + warp * 16 * PST;

    cp_wait1();          // qhi staged
    __syncthreads();
    #pragma unroll
    for (int kk = 0; kk < 8; kk++) {
        const int c = kk * 8 + lr4;
        qh[kk][0] = __float_as_uint(Pw[lq * PST + c]);
        qh[kk][1] = __float_as_uint(Pw[(lq + 8) * PST + c]);
        qh[kk][2] = __float_as_uint(Pw[lq * PST + c + 4]);
        qh[kk][3] = __float_as_uint(Pw[(lq + 8) * PST + c + 4]);
    }
    __syncthreads();
    stage_q(Qlo); cp_commit();
    cp_wait0();          // qlo + kv0 staged
    __syncthreads();
    #pragma unroll
    for (int kk = 0; kk < 8; kk++) {
        const int c = kk * 8 + lr4;
        ql[kk][0] = __float_as_uint(Pw[lq * PST + c]);
        ql[kk][1] = __float_as_uint(Pw[(lq + 8) * PST + c]);
        ql[kk][2] = __float_as_uint(Pw[lq * PST + c + 4]);
        ql[kk][3] = __float_as_uint(Pw[(lq + 8) * PST + c + 4]);
    }
    __syncthreads();

    float oacc[8][4];
    #pragma unroll
    for (int nt = 0; nt < 8; nt++)
        #pragma unroll
        for (int r = 0; r < 4; r++) oacc[nt][r] = 0.f;
    float m0 = -3.0e38f, m1 = -3.0e38f, l0 = 0.f, l1 = 0.f;

    const int row0 = t * 128 + warp * 16 + lq;
    const int row1 = row0 + 8;
    const int nkc = (t == 0) ? (Sseq / 64) : (2 * t + 2);

    for (int kc = 0; kc < nkc; kc++) {
        cp_wait0();
        __syncthreads();
        if (kc + 1 < nkc) { load_kv(kc + 1, (kc + 1) & 1); cp_commit(); }

        const float* KtH = sm + KHI_OFF + (kc & 1) * KTILE;
        const float* KtL = sm + KLO_OFF + (kc & 1) * KTILE;
        const float* VtH = sm + VHI_OFF + (kc & 1) * VTILE;
        const float* VtL = sm + VLO_OFF + (kc & 1) * VTILE;

        // ---- S = Q @ K^T ----
        float sacc[8][4];
        #pragma unroll
        for (int nt = 0; nt < 8; nt++)
            #pragma unroll
            for (int r = 0; r < 4; r++) sacc[nt][r] = 0.f;

        #pragma unroll
        for (int kk = 0; kk < 8; kk++) {
            #pragma unroll
            for (int nt = 0; nt < 8; nt++) {
                const int ko = (nt * 8 + lq) * KST + kk * 8 + lr4;
                uint32_t bh0 = __float_as_uint(KtH[ko]);
                uint32_t bh1 = __float_as_uint(KtH[ko + 4]);
                uint32_t bl0 = __float_as_uint(KtL[ko]);
                uint32_t bl1 = __float_as_uint(KtL[ko + 4]);
                mma_tf32(sacc[nt][0], sacc[nt][1], sacc[nt][2], sacc[nt][3],
                         ql[kk][0], ql[kk][1], ql[kk][2], ql[kk][3], bh0, bh1);
                mma_tf32(sacc[nt][0], sacc[nt][1], sacc[nt][2], sacc[nt][3],
                         qh[kk][0], qh[kk][1], qh[kk][2], qh[kk][3], bl0, bl1);
                mma_tf32(sacc[nt][0], sacc[nt][1], sacc[nt][2], sacc[nt][3],
                         qh[kk][0], qh[kk][1], qh[kk][2], qh[kk][3], bh0, bh1);
            }
        }

        // ---- mask: z >= s -> -1e12 ----
        #pragma unroll
        for (int nt = 0; nt < 8; nt++) {
            const int cb = kc * 64 + nt * 8 + 2 * lr4;
            if (cb     >= row0) sacc[nt][0] = -1.0e12f;
            if (cb + 1 >= row0) sacc[nt][1] = -1.0e12f;
            if (cb     >= row1) sacc[nt][2] = -1.0e12f;
            if (cb + 1 >= row1) sacc[nt][3] = -1.0e12f;
        }

        // ---- online softmax ----
        float mt0 = -3.0e38f, mt1 = -3.0e38f;
        #pragma unroll
        for (int nt = 0; nt < 8; nt++) {
            mt0 = fmaxf(mt0, fmaxf(sacc[nt][0], sacc[nt][1]));
            mt1 = fmaxf(mt1, fmaxf(sacc[nt][2], sacc[nt][3]));
        }
        mt0 = fmaxf(mt0, __shfl_xor_sync(0xffffffffu, mt0, 1));
        mt0 = fmaxf(mt0, __shfl_xor_sync(0xffffffffu, mt0, 2));
        mt1 = fmaxf(mt1, __shfl_xor_sync(0xffffffffu, mt1, 1));
        mt1 = fmaxf(mt1, __shfl_xor_sync(0xffffffffu, mt1, 2));
        const float mn0 = fmaxf(m0, mt0);
        const float mn1 = fmaxf(m1, mt1);
        const float sc0 = __expf(m0 - mn0);
        const float sc1 = __expf(m1 - mn1);
        float ls0 = 0.f, ls1 = 0.f;
        #pragma unroll
        for (int nt = 0; nt < 8; nt++) {
            sacc[nt][0] = __expf(sacc[nt][0] - mn0);
            sacc[nt][1] = __expf(sacc[nt][1] - mn0);
            sacc[nt][2] = __expf(sacc[nt][2] - mn1);
            sacc[nt][3] = __expf(sacc[nt][3] - mn1);
            ls0 += sacc[nt][0] + sacc[nt][1];
            ls1 += sacc[nt][2] + sacc[nt][3];
        }
        l0 = l0 * sc0 + ls0;
        l1 = l1 * sc1 + ls1;
        m0 = mn0; m1 = mn1;
        #pragma unroll
        for (int nt = 0; nt < 8; nt++) {
            oacc[nt][0] *= sc0; oacc[nt][1] *= sc0;
            oacc[nt][2] *= sc1; oacc[nt][3] *= sc1;
        }

        // ---- stage P in per-warp smem stripe ----
        #pragma unroll
        for (int nt = 0; nt < 8; nt++) {
            *(float2*)&Pw[lq * PST + nt * 8 + 2 * lr4] =
                make_float2(sacc[nt][0], sacc[nt][1]);
            *(float2*)&Pw[(lq + 8) * PST + nt * 8 + 2 * lr4] =
                make_float2(sacc[nt][2], sacc[nt][3]);
        }
        __syncwarp();

        // ---- O += P_hi @ (V_hi + V_lo) ----
        #pragma unroll
        for (int kk = 0; kk < 8; kk++) {
            const int c = kk * 8 + lr4;
            uint32_t ph[4];
            ph[0] = f2tf32(Pw[lq * PST + c]);
            ph[1] = f2tf32(Pw[(lq + 8) * PST + c]);
            ph[2] = f2tf32(Pw[lq * PST + c + 4]);
            ph[3] = f2tf32(Pw[(lq + 8) * PST + c + 4]);
            #pragma unroll
            for (int nt = 0; nt < 8; nt++) {
                const int v0o = (kk * 8 + lr4) * VST + nt * 8 + lq;
                const int v1o = (kk * 8 + lr4 + 4) * VST + nt * 8 + lq;
                uint32_t vh0 = __float_as_uint(VtH[v0o]);
                uint32_t vh1 = __float_as_uint(VtH[v1o]);
                uint32_t vl0 = __float_as_uint(VtL[v0o]);
                uint32_t vl1 = __float_as_uint(VtL[v1o]);
                mma_tf32(oacc[nt][0], oacc[nt][1], oacc[nt][2], oacc[nt][3],
                         ph[0], ph[1], ph[2], ph[3], vl0, vl1);
                mma_tf32(oacc[nt][0], oacc[nt][1], oacc[nt][2], oacc[nt][3],
                         ph[0], ph[1], ph[2], ph[3], vh0, vh1);
            }
        }
        __syncwarp();
    }

    // ---- epilogue ----
    l0 += __shfl_xor_sync(0xffffffffu, l0, 1);
    l0 += __shfl_xor_sync(0xffffffffu, l0, 2);
    l1 += __shfl_xor_sync(0xffffffffu, l1, 1);
    l1 += __shfl_xor_sync(0xffffffffu, l1, 2);
    const float inv0 = 1.f / l0;
    const float inv1 = 1.f / l1;

    float* Og = O + ((size_t)b * Sseq + (size_t)t * 128 + warp * 16) * Fdim + h * Dh;
    #pragma unroll
    for (int nt = 0; nt < 8; nt++) {
        const int cb = nt * 8 + 2 * lr4;
        *(float2*)&Og[(size_t)lq * Fdim + cb] =
            make_float2(oacc[nt][0] * inv0, oacc[nt][1] * inv0);
        *(float2*)&Og[(size_t)(lq + 8) * Fdim + cb] =
            make_float2(oacc[nt][2] * inv1, oacc[nt][3] * inv1);
    }
}

// ---------------------------------------------------------------------------
extern "C" void kernel_launch(void* const* d_in, const int* in_sizes, int n_in,
                              void* d_out, int out_size)
{
    (void)in_sizes; (void)n_in; (void)out_size;
    const float* attend_from = (const float*)d_in[0];
    const float* attend_to   = (const float*)d_in[1];
    const float* w_q   = (const float*)d_in[2];
    const float* b_q   = (const float*)d_in[3];
    const float* w_kv  = (const float*)d_in[4];
    const float* b_kv  = (const float*)d_in[5];
    const float* w_out = (const float*)d_in[6];
    const float* b_out = (const float*)d_in[7];
    float* out = (float*)d_out;

    float *qhi, *qlo, *khi, *klo, *vhi, *vlo, *Op;
    cudaGetSymbolAddress((void**)&qhi, g_Qhi);
    cudaGetSymbolAddress((void**)&qlo, g_Qlo);
    cudaGetSymbolAddress((void**)&khi, g_Khi);
    cudaGetSymbolAddress((void**)&klo, g_Klo);
    cudaGetSymbolAddress((void**)&vhi, g_Vhi);
    cudaGetSymbolAddress((void**)&vlo, g_Vlo);
    cudaGetSymbolAddress((void**)&Op,  g_O);

    cudaFuncSetAttribute(qkv_gemm_kernel,
                         cudaFuncAttributeMaxDynamicSharedMemorySize, GEMM_SMEM);
    cudaFuncSetAttribute(out_gemm_kernel,
                         cudaFuncAttributeMaxDynamicSharedMemorySize, GEMM_SMEM);
    cudaFuncSetAttribute(flash_mma_kernel,
                         cudaFuncAttributeMaxDynamicSharedMemorySize, FLASH_SMEM);

    // 1) Q + KV projections, merged (768 CTAs), split-stored as tf32 hi/lo
    qkv_gemm_kernel<<<768, 256, GEMM_SMEM>>>(
        attend_from, attend_to, w_q, w_kv, b_q, b_kv,
        qhi, qlo, khi, klo, vhi, vlo);

    // 2) Tensor-core flash attention on pre-split operands
    {
        dim3 grid(Sseq / 128, Hh, Bsz);
        flash_mma_kernel<<<grid, 256, FLASH_SMEM>>>(
            qhi, qlo, khi, klo, vhi, vlo, Op);
    }

    // 3) Output projection
    {
        dim3 grid(Fdim / 128, Mrows / 128);
        out_gemm_kernel<<<grid, 256, GEMM_SMEM>>>(Op, w_out, b_out, out);
    }
}